// round 1
// baseline (speedup 1.0000x reference)
#include <cuda_runtime.h>
#include <cuda_bf16.h>

#define N_TOTAL   1000000
#define DIM       128
#define S_SEG     125000
#define SEG_TILE  64
#define S_PAD     125056          // 1954 * 64
#define N_TILES   1954
#define EPS       1e-13f
#define NODES_PER_WARP 128

// Scratch (device globals: no allocation allowed)
__device__ float g_Z[(size_t)S_PAD * DIM];   // unnormalized weighted sums, 64 MB
__device__ float g_denom[S_PAD];

// ---------------------------------------------------------------------------
// Kernel 1: zero scratch
// ---------------------------------------------------------------------------
__global__ void zero_scratch_kernel() {
    const size_t nz4 = (size_t)S_PAD * DIM / 4;
    float4* z4 = reinterpret_cast<float4*>(g_Z);
    float4 zero = make_float4(0.f, 0.f, 0.f, 0.f);
    for (size_t i = (size_t)blockIdx.x * blockDim.x + threadIdx.x;
         i < nz4; i += (size_t)gridDim.x * blockDim.x)
        z4[i] = zero;
    const size_t nd4 = S_PAD / 4;
    float4* d4 = reinterpret_cast<float4*>(g_denom);
    for (size_t i = (size_t)blockIdx.x * blockDim.x + threadIdx.x;
         i < nd4; i += (size_t)gridDim.x * blockDim.x)
        d4[i] = zero;
}

// ---------------------------------------------------------------------------
// Kernel 2: fused gate + segment accumulation.
// One warp handles NODES_PER_WARP contiguous nodes. index is sorted, so each
// warp accumulates the current segment in registers and flushes with atomics
// only on segment change / warp boundary.
// ---------------------------------------------------------------------------
__device__ __forceinline__ void flush_seg(int seg, const float4& acc, float esum, int lane) {
    float* zp = &g_Z[(size_t)seg * DIM + lane * 4];
    atomicAdd(zp + 0, acc.x);
    atomicAdd(zp + 1, acc.y);
    atomicAdd(zp + 2, acc.z);
    atomicAdd(zp + 3, acc.w);
    if (lane == 0) atomicAdd(&g_denom[seg], esum);
}

__global__ void __launch_bounds__(256)
pass1_kernel(const float* __restrict__ x,
             const int*   __restrict__ index,
             const float* __restrict__ weights,
             const float* __restrict__ Wg,
             const float* __restrict__ bg)
{
    const int warp_id = (blockIdx.x * blockDim.x + threadIdx.x) >> 5;
    const int lane    = threadIdx.x & 31;

    int start = warp_id * NODES_PER_WARP;
    if (start >= N_TOTAL) return;
    int end = min(start + NODES_PER_WARP, N_TOTAL);

    const float4 wg  = reinterpret_cast<const float4*>(Wg)[lane];
    const float  bg0 = __ldg(bg);
    const float4* __restrict__ x4 = reinterpret_cast<const float4*>(x);

    int    cur  = __ldg(&index[start]);
    float4 acc  = make_float4(0.f, 0.f, 0.f, 0.f);
    float  esum = 0.f;

    for (int n = start; n < end; ++n) {
        float4 xv  = x4[(size_t)n * 32 + lane];
        int    seg = __ldg(&index[n]);                 // broadcast
        float  wn  = __ldg(&weights[n]);               // broadcast

        float dot = xv.x * wg.x + xv.y * wg.y + xv.z * wg.z + xv.w * wg.w;
        #pragma unroll
        for (int o = 16; o; o >>= 1)
            dot += __shfl_xor_sync(0xFFFFFFFFu, dot, o);

        float e = wn * __expf(dot + bg0);

        if (seg != cur) {
            flush_seg(cur, acc, esum, lane);
            cur = seg;
            acc = make_float4(0.f, 0.f, 0.f, 0.f);
            esum = 0.f;
        }
        acc.x += e * xv.x;
        acc.y += e * xv.y;
        acc.z += e * xv.z;
        acc.w += e * xv.w;
        esum  += e;
    }
    flush_seg(cur, acc, esum, lane);
}

// ---------------------------------------------------------------------------
// Kernel 3: out[s][:] = (Z[s][:] / (denom+EPS)) @ Wm + (denom/(denom+EPS))*bm
// Tile: 64 segments x 128 cols per block, K chunked by 32.
// 256 threads, each computes 4 segs x 8 cols (32 accumulators).
// ---------------------------------------------------------------------------
__global__ void __launch_bounds__(256)
gemm_kernel(const float* __restrict__ Wm,
            const float* __restrict__ bm,
            float*       __restrict__ out)
{
    __shared__ float Wms[32][DIM];      // 16 KB  (k-chunk rows x all 128 cols)
    __shared__ float Zs[32][SEG_TILE + 1]; // 8.25 KB, transposed, padded

    const int t  = threadIdx.x;
    const int tx = t & 15;              // col group: cols tx*8 .. tx*8+7
    const int ty = t >> 4;              // seg group: segs ty, ty+16, ty+32, ty+48
    const int s0 = blockIdx.x * SEG_TILE;

    float acc[4][8];
    #pragma unroll
    for (int q = 0; q < 4; ++q)
        #pragma unroll
        for (int r = 0; r < 8; ++r) acc[q][r] = 0.f;

    for (int kc = 0; kc < DIM; kc += 32) {
        // load Wm chunk [kc..kc+31][0..127], vectorized
        #pragma unroll
        for (int i = 0; i < 4; ++i) {
            int f   = t + i * 256;          // 0..1023 float4s
            int row = f >> 5;               // 0..31
            int c4  = f & 31;               // 0..31 float4 within row
            reinterpret_cast<float4*>(&Wms[row][0])[c4] =
                reinterpret_cast<const float4*>(Wm + (size_t)(kc + row) * DIM)[c4];
        }
        // load Z chunk [s0..s0+63][kc..kc+31] transposed into Zs[k][m]
        #pragma unroll
        for (int i = 0; i < 8; ++i) {
            int e  = t + i * 256;           // 0..2047
            int m  = e >> 5;                // seg local 0..63
            int k  = e & 31;                // k local 0..31
            Zs[k][m] = g_Z[(size_t)(s0 + m) * DIM + kc + k];
        }
        __syncthreads();

        #pragma unroll
        for (int k = 0; k < 32; ++k) {
            float a0 = Zs[k][ty];
            float a1 = Zs[k][ty + 16];
            float a2 = Zs[k][ty + 32];
            float a3 = Zs[k][ty + 48];
            float4 b0 = *reinterpret_cast<const float4*>(&Wms[k][tx * 8]);
            float4 b1 = *reinterpret_cast<const float4*>(&Wms[k][tx * 8 + 4]);
            float bb[8] = {b0.x, b0.y, b0.z, b0.w, b1.x, b1.y, b1.z, b1.w};
            #pragma unroll
            for (int r = 0; r < 8; ++r) {
                acc[0][r] += a0 * bb[r];
                acc[1][r] += a1 * bb[r];
                acc[2][r] += a2 * bb[r];
                acc[3][r] += a3 * bb[r];
            }
        }
        __syncthreads();
    }

    // epilogue
    const int j = tx * 8;
    float bmv[8];
    #pragma unroll
    for (int r = 0; r < 8; ++r) bmv[r] = __ldg(&bm[j + r]);

    #pragma unroll
    for (int q = 0; q < 4; ++q) {
        int s = s0 + ty + q * 16;
        if (s >= S_SEG) continue;
        float den  = g_denom[s];
        float inv  = 1.0f / (den + EPS);
        float frac = den * inv;
        float4 o0, o1;
        o0.x = acc[q][0] * inv + frac * bmv[0];
        o0.y = acc[q][1] * inv + frac * bmv[1];
        o0.z = acc[q][2] * inv + frac * bmv[2];
        o0.w = acc[q][3] * inv + frac * bmv[3];
        o1.x = acc[q][4] * inv + frac * bmv[4];
        o1.y = acc[q][5] * inv + frac * bmv[5];
        o1.z = acc[q][6] * inv + frac * bmv[6];
        o1.w = acc[q][7] * inv + frac * bmv[7];
        float* op = out + (size_t)s * DIM + j;
        *reinterpret_cast<float4*>(op)     = o0;
        *reinterpret_cast<float4*>(op + 4) = o1;
    }
}

// ---------------------------------------------------------------------------
// Launch: inputs (metadata order): x, index, weights, Wg, bg, Wm, bm
// ---------------------------------------------------------------------------
extern "C" void kernel_launch(void* const* d_in, const int* in_sizes, int n_in,
                              void* d_out, int out_size)
{
    const float* x       = (const float*)d_in[0];
    const int*   index   = (const int*)  d_in[1];
    const float* weights = (const float*)d_in[2];
    const float* Wg      = (const float*)d_in[3];
    const float* bg      = (const float*)d_in[4];
    const float* Wm      = (const float*)d_in[5];
    const float* bm      = (const float*)d_in[6];
    float*       out     = (float*)d_out;

    zero_scratch_kernel<<<2048, 256>>>();

    const int n_warps  = (N_TOTAL + NODES_PER_WARP - 1) / NODES_PER_WARP; // 7813
    const int n_blocks = (n_warps + 7) / 8;                               // 977
    pass1_kernel<<<n_blocks, 256>>>(x, index, weights, Wg, bg);

    gemm_kernel<<<N_TILES, 256>>>(Wm, bm, out);
}

// round 9
// speedup vs baseline: 1.5530x; 1.5530x over previous
#include <cuda_runtime.h>
#include <cuda_bf16.h>
#include <mma.h>

using namespace nvcuda;

#define N_TOTAL   1000000
#define DIM       128
#define S_SEG     125000
#define S_PAD     125056
#define EPS       1e-13f
#define NODES_PER_WARP 128

// Scratch (device globals: no allocation allowed)
__device__ float g_Z[(size_t)S_PAD * DIM];   // unnormalized weighted sums, 64 MB
__device__ float g_denom[S_PAD];

// ---------------------------------------------------------------------------
// Kernel 1: zero scratch
// ---------------------------------------------------------------------------
__global__ void zero_scratch_kernel() {
    const size_t nz4 = (size_t)S_PAD * DIM / 4;
    float4* z4 = reinterpret_cast<float4*>(g_Z);
    float4 zero = make_float4(0.f, 0.f, 0.f, 0.f);
    for (size_t i = (size_t)blockIdx.x * blockDim.x + threadIdx.x;
         i < nz4; i += (size_t)gridDim.x * blockDim.x)
        z4[i] = zero;
    const size_t nd4 = S_PAD / 4;
    float4* d4 = reinterpret_cast<float4*>(g_denom);
    for (size_t i = (size_t)blockIdx.x * blockDim.x + threadIdx.x;
         i < nd4; i += (size_t)gridDim.x * blockDim.x)
        d4[i] = zero;
}

// ---------------------------------------------------------------------------
// Kernel 2: fused gate + segment accumulation.
// One warp handles 128 contiguous nodes, 4 at a time (interleaved shuffle
// reductions pipeline across the 4 independent dots). index is sorted, so
// each warp accumulates the current segment in registers and flushes with
// atomics only on segment change / warp boundary.
// ---------------------------------------------------------------------------
__device__ __forceinline__ void flush_seg(int seg, const float4& acc, float esum, int lane) {
    float* zp = &g_Z[(size_t)seg * DIM + lane * 4];
    atomicAdd(zp + 0, acc.x);
    atomicAdd(zp + 1, acc.y);
    atomicAdd(zp + 2, acc.z);
    atomicAdd(zp + 3, acc.w);
    if (lane == 0) atomicAdd(&g_denom[seg], esum);
}

__global__ void __launch_bounds__(256)
pass1_kernel(const float* __restrict__ x,
             const int*   __restrict__ index,
             const float* __restrict__ weights,
             const float* __restrict__ Wg,
             const float* __restrict__ bg)
{
    const int warp_id = (blockIdx.x * blockDim.x + threadIdx.x) >> 5;
    const int lane    = threadIdx.x & 31;

    int start = warp_id * NODES_PER_WARP;
    if (start >= N_TOTAL) return;
    int end = min(start + NODES_PER_WARP, N_TOTAL);

    const float4 wg  = reinterpret_cast<const float4*>(Wg)[lane];
    const float  bg0 = __ldg(bg);
    const float4* __restrict__ x4 = reinterpret_cast<const float4*>(x);

    int    cur  = __ldg(&index[start]);
    float4 acc  = make_float4(0.f, 0.f, 0.f, 0.f);
    float  esum = 0.f;

    // N_TOTAL % 4 == 0 and NODES_PER_WARP % 4 == 0 => (end-start) % 4 == 0
    for (int n = start; n < end; n += 4) {
        // batch loads: high MLP
        float4 xv0 = x4[(size_t)(n + 0) * 32 + lane];
        float4 xv1 = x4[(size_t)(n + 1) * 32 + lane];
        float4 xv2 = x4[(size_t)(n + 2) * 32 + lane];
        float4 xv3 = x4[(size_t)(n + 3) * 32 + lane];
        int sg0 = __ldg(&index[n + 0]);
        int sg1 = __ldg(&index[n + 1]);
        int sg2 = __ldg(&index[n + 2]);
        int sg3 = __ldg(&index[n + 3]);
        float w0 = __ldg(&weights[n + 0]);
        float w1 = __ldg(&weights[n + 1]);
        float w2 = __ldg(&weights[n + 2]);
        float w3 = __ldg(&weights[n + 3]);

        float d0 = xv0.x * wg.x + xv0.y * wg.y + xv0.z * wg.z + xv0.w * wg.w;
        float d1 = xv1.x * wg.x + xv1.y * wg.y + xv1.z * wg.z + xv1.w * wg.w;
        float d2 = xv2.x * wg.x + xv2.y * wg.y + xv2.z * wg.z + xv2.w * wg.w;
        float d3 = xv3.x * wg.x + xv3.y * wg.y + xv3.z * wg.z + xv3.w * wg.w;

        // interleaved butterfly reductions: 4 independent chains pipeline
        #pragma unroll
        for (int o = 16; o; o >>= 1) {
            d0 += __shfl_xor_sync(0xFFFFFFFFu, d0, o);
            d1 += __shfl_xor_sync(0xFFFFFFFFu, d1, o);
            d2 += __shfl_xor_sync(0xFFFFFFFFu, d2, o);
            d3 += __shfl_xor_sync(0xFFFFFFFFu, d3, o);
        }

        float e0 = w0 * __expf(d0 + bg0);
        float e1 = w1 * __expf(d1 + bg0);
        float e2 = w2 * __expf(d2 + bg0);
        float e3 = w3 * __expf(d3 + bg0);

        auto step = [&](int seg, float e, const float4& xv) {
            if (seg != cur) {
                flush_seg(cur, acc, esum, lane);
                cur = seg;
                acc = make_float4(0.f, 0.f, 0.f, 0.f);
                esum = 0.f;
            }
            acc.x += e * xv.x;
            acc.y += e * xv.y;
            acc.z += e * xv.z;
            acc.w += e * xv.w;
            esum += e;
        };
        step(sg0, e0, xv0);
        step(sg1, e1, xv1);
        step(sg2, e2, xv2);
        step(sg3, e3, xv3);
    }
    flush_seg(cur, acc, esum, lane);
}

// ---------------------------------------------------------------------------
// Kernel 3: tensor-core GEMM with 2-term bf16 split (error ~2^-18).
//   out[s][:] = (Z[s][:] * inv[s]) @ Wm + frac[s] * bm
// A rows are scaled by inv during the smem load/convert; the bias term is
// folded in as one extra K=16 MMA step (A col0 = frac, B row0 = bm).
// Block: 128 segments x 128 cols, K chunked by 32, 8 warps (16 rows each).
// ---------------------------------------------------------------------------
__device__ __forceinline__ void bf16_split(float v, __nv_bfloat16& hi, __nv_bfloat16& lo) {
    hi = __float2bfloat16(v);
    lo = __float2bfloat16(v - __bfloat162float(hi));
}

__global__ void __launch_bounds__(256)
gemm_tc_kernel(const float* __restrict__ Wm,
               const float* __restrict__ bm,
               float*       __restrict__ out)
{
    __shared__ __nv_bfloat16 Ahi[128][40];   // ld=40 elems (80B, mult of 16)
    __shared__ __nv_bfloat16 Alo[128][40];
    __shared__ __nv_bfloat16 Bhi[32][136];   // ld=136 elems (272B, mult of 16)
    __shared__ __nv_bfloat16 Blo[32][136];
    __shared__ float s_inv[128];
    __shared__ float s_frac[128];

    const int t   = threadIdx.x;
    const int wid = t >> 5;
    // clamp so the last block overlaps the previous one instead of running
    // past S_SEG (overlapping rows are written twice with identical values)
    const int s0  = min(blockIdx.x * 128, S_SEG - 128);

    if (t < 128) {
        float d  = g_denom[s0 + t];
        float iv = 1.0f / (d + EPS);
        s_inv[t]  = iv;
        s_frac[t] = d * iv;
    }
    __syncthreads();

    wmma::fragment<wmma::accumulator, 16, 16, 16, float> acc[8];
    #pragma unroll
    for (int nt = 0; nt < 8; ++nt) wmma::fill_fragment(acc[nt], 0.0f);

    wmma::fragment<wmma::matrix_a, 16, 16, 16, __nv_bfloat16, wmma::row_major> a_hi, a_lo;
    wmma::fragment<wmma::matrix_b, 16, 16, 16, __nv_bfloat16, wmma::row_major> b_hi, b_lo;

    for (int kc = 0; kc < DIM; kc += 32) {
        // load & convert A chunk [128 rows][32 k] (scaled by inv): 1024 float4
        #pragma unroll
        for (int i = 0; i < 4; ++i) {
            int f   = t + i * 256;
            int row = f >> 3;
            int c0  = (f & 7) * 4;
            float4 v = *reinterpret_cast<const float4*>(
                &g_Z[(size_t)(s0 + row) * DIM + kc + c0]);
            float iv = s_inv[row];
            v.x *= iv; v.y *= iv; v.z *= iv; v.w *= iv;
            bf16_split(v.x, Ahi[row][c0 + 0], Alo[row][c0 + 0]);
            bf16_split(v.y, Ahi[row][c0 + 1], Alo[row][c0 + 1]);
            bf16_split(v.z, Ahi[row][c0 + 2], Alo[row][c0 + 2]);
            bf16_split(v.w, Ahi[row][c0 + 3], Alo[row][c0 + 3]);
        }
        // load & convert B chunk [32 k][128 cols]: 1024 float4
        #pragma unroll
        for (int i = 0; i < 4; ++i) {
            int f   = t + i * 256;
            int row = f >> 5;
            int c0  = (f & 31) * 4;
            float4 v = *reinterpret_cast<const float4*>(
                &Wm[(size_t)(kc + row) * DIM + c0]);
            bf16_split(v.x, Bhi[row][c0 + 0], Blo[row][c0 + 0]);
            bf16_split(v.y, Bhi[row][c0 + 1], Blo[row][c0 + 1]);
            bf16_split(v.z, Bhi[row][c0 + 2], Blo[row][c0 + 2]);
            bf16_split(v.w, Bhi[row][c0 + 3], Blo[row][c0 + 3]);
        }
        __syncthreads();

        #pragma unroll
        for (int ks = 0; ks < 2; ++ks) {
            wmma::load_matrix_sync(a_hi, &Ahi[wid * 16][ks * 16], 40);
            wmma::load_matrix_sync(a_lo, &Alo[wid * 16][ks * 16], 40);
            #pragma unroll
            for (int nt = 0; nt < 8; ++nt) {
                wmma::load_matrix_sync(b_hi, &Bhi[ks * 16][nt * 16], 136);
                wmma::load_matrix_sync(b_lo, &Blo[ks * 16][nt * 16], 136);
                wmma::mma_sync(acc[nt], a_hi, b_hi, acc[nt]);
                wmma::mma_sync(acc[nt], a_lo, b_hi, acc[nt]);
                wmma::mma_sync(acc[nt], a_hi, b_lo, acc[nt]);
            }
        }
        __syncthreads();
    }

    // --- bias step: out += frac[row] * bm[col], as one K=16 MMA ---
    for (int idx = t; idx < 128 * 16; idx += 256) {
        int r = idx >> 4, c = idx & 15;
        float v = (c == 0) ? s_frac[r] : 0.0f;
        bf16_split(v, Ahi[r][c], Alo[r][c]);
    }
    for (int idx = t; idx < 16 * 128; idx += 256) {
        int r = idx >> 7, c = idx & 127;
        float v = (r == 0) ? __ldg(&bm[c]) : 0.0f;
        bf16_split(v, Bhi[r][c], Blo[r][c]);
    }
    __syncthreads();

    wmma::load_matrix_sync(a_hi, &Ahi[wid * 16][0], 40);
    wmma::load_matrix_sync(a_lo, &Alo[wid * 16][0], 40);
    #pragma unroll
    for (int nt = 0; nt < 8; ++nt) {
        wmma::load_matrix_sync(b_hi, &Bhi[0][nt * 16], 136);
        wmma::load_matrix_sync(b_lo, &Blo[0][nt * 16], 136);
        wmma::mma_sync(acc[nt], a_hi, b_hi, acc[nt]);
        wmma::mma_sync(acc[nt], a_lo, b_hi, acc[nt]);
        wmma::mma_sync(acc[nt], a_hi, b_lo, acc[nt]);
    }

    // direct store (all rows valid thanks to the s0 clamp)
    #pragma unroll
    for (int nt = 0; nt < 8; ++nt) {
        wmma::store_matrix_sync(out + (size_t)(s0 + wid * 16) * DIM + nt * 16,
                                acc[nt], DIM, wmma::mem_row_major);
    }
}

// ---------------------------------------------------------------------------
// Launch: inputs (metadata order): x, index, weights, Wg, bg, Wm, bm
// ---------------------------------------------------------------------------
extern "C" void kernel_launch(void* const* d_in, const int* in_sizes, int n_in,
                              void* d_out, int out_size)
{
    const float* x       = (const float*)d_in[0];
    const int*   index   = (const int*)  d_in[1];
    const float* weights = (const float*)d_in[2];
    const float* Wg      = (const float*)d_in[3];
    const float* bg      = (const float*)d_in[4];
    const float* Wm      = (const float*)d_in[5];
    const float* bm      = (const float*)d_in[6];
    float*       out     = (float*)d_out;

    zero_scratch_kernel<<<4096, 256>>>();

    const int n_warps  = (N_TOTAL + NODES_PER_WARP - 1) / NODES_PER_WARP; // 7813
    const int n_blocks = (n_warps + 7) / 8;                               // 977
    pass1_kernel<<<n_blocks, 256>>>(x, index, weights, Wg, bg);

    const int gemm_blocks = (S_SEG + 127) / 128;                          // 977
    gemm_tc_kernel<<<gemm_blocks, 256>>>(Wm, bm, out);
}

// round 10
// speedup vs baseline: 1.6063x; 1.0343x over previous
#include <cuda_runtime.h>
#include <cuda_bf16.h>
#include <mma.h>

using namespace nvcuda;

#define N_TOTAL   1000000
#define DIM       128
#define S_SEG     125000
#define S_PAD     125056
#define EPS       1e-13f
#define NODES_PER_WARP 128

// Scratch (device globals: no allocation allowed)
__device__ float g_Z[(size_t)S_PAD * DIM];   // unnormalized weighted sums, 64 MB
__device__ float g_denom[S_PAD];

// ---------------------------------------------------------------------------
// Kernel 1: zero scratch
// ---------------------------------------------------------------------------
__global__ void zero_scratch_kernel() {
    const size_t nz4 = (size_t)S_PAD * DIM / 4;
    float4* z4 = reinterpret_cast<float4*>(g_Z);
    float4 zero = make_float4(0.f, 0.f, 0.f, 0.f);
    for (size_t i = (size_t)blockIdx.x * blockDim.x + threadIdx.x;
         i < nz4; i += (size_t)gridDim.x * blockDim.x)
        z4[i] = zero;
    const size_t nd4 = S_PAD / 4;
    float4* d4 = reinterpret_cast<float4*>(g_denom);
    for (size_t i = (size_t)blockIdx.x * blockDim.x + threadIdx.x;
         i < nd4; i += (size_t)gridDim.x * blockDim.x)
        d4[i] = zero;
}

// ---------------------------------------------------------------------------
// Kernel 2: fused gate + segment accumulation.
// One warp handles 128 contiguous nodes, 4 at a time. Flushes use vectorized
// red.global.add.v4.f32 (16B L2 atomic transactions instead of 4x4B), and a
// fast path skips per-node branches when all 4 nodes share the segment.
// ---------------------------------------------------------------------------
__device__ __forceinline__ void flush_seg(int seg, const float4& acc, float esum, int lane) {
    float* zp = &g_Z[(size_t)seg * DIM + lane * 4];
    asm volatile("red.global.add.v4.f32 [%0], {%1, %2, %3, %4};"
                 :: "l"(zp), "f"(acc.x), "f"(acc.y), "f"(acc.z), "f"(acc.w)
                 : "memory");
    if (lane == 0) atomicAdd(&g_denom[seg], esum);
}

__global__ void __launch_bounds__(256)
pass1_kernel(const float* __restrict__ x,
             const int*   __restrict__ index,
             const float* __restrict__ weights,
             const float* __restrict__ Wg,
             const float* __restrict__ bg)
{
    const int warp_id = (blockIdx.x * blockDim.x + threadIdx.x) >> 5;
    const int lane    = threadIdx.x & 31;

    int start = warp_id * NODES_PER_WARP;
    if (start >= N_TOTAL) return;
    int end = min(start + NODES_PER_WARP, N_TOTAL);

    const float4 wg  = reinterpret_cast<const float4*>(Wg)[lane];
    const float  bg0 = __ldg(bg);
    const float4* __restrict__ x4 = reinterpret_cast<const float4*>(x);

    int    cur  = __ldg(&index[start]);
    float4 acc  = make_float4(0.f, 0.f, 0.f, 0.f);
    float  esum = 0.f;

    // N_TOTAL % 4 == 0 and NODES_PER_WARP % 4 == 0 => (end-start) % 4 == 0
    for (int n = start; n < end; n += 4) {
        // batch loads: high MLP
        float4 xv0 = x4[(size_t)(n + 0) * 32 + lane];
        float4 xv1 = x4[(size_t)(n + 1) * 32 + lane];
        float4 xv2 = x4[(size_t)(n + 2) * 32 + lane];
        float4 xv3 = x4[(size_t)(n + 3) * 32 + lane];
        int sg0 = __ldg(&index[n + 0]);
        int sg1 = __ldg(&index[n + 1]);
        int sg2 = __ldg(&index[n + 2]);
        int sg3 = __ldg(&index[n + 3]);
        float w0 = __ldg(&weights[n + 0]);
        float w1 = __ldg(&weights[n + 1]);
        float w2 = __ldg(&weights[n + 2]);
        float w3 = __ldg(&weights[n + 3]);

        float d0 = xv0.x * wg.x + xv0.y * wg.y + xv0.z * wg.z + xv0.w * wg.w;
        float d1 = xv1.x * wg.x + xv1.y * wg.y + xv1.z * wg.z + xv1.w * wg.w;
        float d2 = xv2.x * wg.x + xv2.y * wg.y + xv2.z * wg.z + xv2.w * wg.w;
        float d3 = xv3.x * wg.x + xv3.y * wg.y + xv3.z * wg.z + xv3.w * wg.w;

        // interleaved butterfly reductions: 4 independent chains pipeline
        #pragma unroll
        for (int o = 16; o; o >>= 1) {
            d0 += __shfl_xor_sync(0xFFFFFFFFu, d0, o);
            d1 += __shfl_xor_sync(0xFFFFFFFFu, d1, o);
            d2 += __shfl_xor_sync(0xFFFFFFFFu, d2, o);
            d3 += __shfl_xor_sync(0xFFFFFFFFu, d3, o);
        }

        float e0 = w0 * __expf(d0 + bg0);
        float e1 = w1 * __expf(d1 + bg0);
        float e2 = w2 * __expf(d2 + bg0);
        float e3 = w3 * __expf(d3 + bg0);

        // fast path: sorted index => sg0==cur && sg3==cur implies all 4 equal
        if ((sg0 == cur) && (sg3 == cur)) {
            acc.x += e0 * xv0.x + e1 * xv1.x + e2 * xv2.x + e3 * xv3.x;
            acc.y += e0 * xv0.y + e1 * xv1.y + e2 * xv2.y + e3 * xv3.y;
            acc.z += e0 * xv0.z + e1 * xv1.z + e2 * xv2.z + e3 * xv3.z;
            acc.w += e0 * xv0.w + e1 * xv1.w + e2 * xv2.w + e3 * xv3.w;
            esum  += e0 + e1 + e2 + e3;
        } else {
            auto step = [&](int seg, float e, const float4& xv) {
                if (seg != cur) {
                    flush_seg(cur, acc, esum, lane);
                    cur = seg;
                    acc = make_float4(0.f, 0.f, 0.f, 0.f);
                    esum = 0.f;
                }
                acc.x += e * xv.x;
                acc.y += e * xv.y;
                acc.z += e * xv.z;
                acc.w += e * xv.w;
                esum += e;
            };
            step(sg0, e0, xv0);
            step(sg1, e1, xv1);
            step(sg2, e2, xv2);
            step(sg3, e3, xv3);
        }
    }
    flush_seg(cur, acc, esum, lane);
}

// ---------------------------------------------------------------------------
// Kernel 3: tensor-core GEMM with 2-term bf16 split (error ~2^-18).
//   out[s][:] = (Z[s][:] * inv[s]) @ Wm + frac[s] * bm
// Converts use packed bf16x2 (one CVT + one 32-bit STS per 2 elements).
// Block: 128 segments x 128 cols, K chunked by 32, 8 warps (16 rows each).
// ---------------------------------------------------------------------------
__device__ __forceinline__ void bf16_split(float v, __nv_bfloat16& hi, __nv_bfloat16& lo) {
    hi = __float2bfloat16(v);
    lo = __float2bfloat16(v - __bfloat162float(hi));
}

// packed split of a pair (a,b): writes hi2/lo2 as 32-bit words
__device__ __forceinline__ void bf16_split2(float a, float b,
                                            __nv_bfloat162& hi2, __nv_bfloat162& lo2) {
    hi2 = __float22bfloat162_rn(make_float2(a, b));
    float2 hf = __bfloat1622float2(hi2);
    lo2 = __float22bfloat162_rn(make_float2(a - hf.x, b - hf.y));
}

__global__ void __launch_bounds__(256)
gemm_tc_kernel(const float* __restrict__ Wm,
               const float* __restrict__ bm,
               float*       __restrict__ out)
{
    __shared__ __nv_bfloat16 Ahi[128][40];   // ld=40 elems (80B, mult of 16)
    __shared__ __nv_bfloat16 Alo[128][40];
    __shared__ __nv_bfloat16 Bhi[32][136];   // ld=136 elems (272B, mult of 16)
    __shared__ __nv_bfloat16 Blo[32][136];
    __shared__ float s_inv[128];
    __shared__ float s_frac[128];

    const int t   = threadIdx.x;
    const int wid = t >> 5;
    // clamp so the last block overlaps the previous one instead of running
    // past S_SEG (overlapping rows are written twice with identical values)
    const int s0  = min(blockIdx.x * 128, S_SEG - 128);

    if (t < 128) {
        float d  = g_denom[s0 + t];
        float iv = 1.0f / (d + EPS);
        s_inv[t]  = iv;
        s_frac[t] = d * iv;
    }
    __syncthreads();

    wmma::fragment<wmma::accumulator, 16, 16, 16, float> acc[8];
    #pragma unroll
    for (int nt = 0; nt < 8; ++nt) wmma::fill_fragment(acc[nt], 0.0f);

    wmma::fragment<wmma::matrix_a, 16, 16, 16, __nv_bfloat16, wmma::row_major> a_hi, a_lo;
    wmma::fragment<wmma::matrix_b, 16, 16, 16, __nv_bfloat16, wmma::row_major> b_hi, b_lo;

    for (int kc = 0; kc < DIM; kc += 32) {
        // load & convert A chunk [128 rows][32 k] (scaled by inv): 1024 float4
        #pragma unroll
        for (int i = 0; i < 4; ++i) {
            int f   = t + i * 256;
            int row = f >> 3;
            int c0  = (f & 7) * 4;            // multiple of 4 -> 8B smem alignment
            float4 v = *reinterpret_cast<const float4*>(
                &g_Z[(size_t)(s0 + row) * DIM + kc + c0]);
            float iv = s_inv[row];
            v.x *= iv; v.y *= iv; v.z *= iv; v.w *= iv;
            __nv_bfloat162 h01, l01, h23, l23;
            bf16_split2(v.x, v.y, h01, l01);
            bf16_split2(v.z, v.w, h23, l23);
            *reinterpret_cast<__nv_bfloat162*>(&Ahi[row][c0])     = h01;
            *reinterpret_cast<__nv_bfloat162*>(&Ahi[row][c0 + 2]) = h23;
            *reinterpret_cast<__nv_bfloat162*>(&Alo[row][c0])     = l01;
            *reinterpret_cast<__nv_bfloat162*>(&Alo[row][c0 + 2]) = l23;
        }
        // load & convert B chunk [32 k][128 cols]: 1024 float4
        #pragma unroll
        for (int i = 0; i < 4; ++i) {
            int f   = t + i * 256;
            int row = f >> 5;
            int c0  = (f & 31) * 4;
            float4 v = *reinterpret_cast<const float4*>(
                &Wm[(size_t)(kc + row) * DIM + c0]);
            __nv_bfloat162 h01, l01, h23, l23;
            bf16_split2(v.x, v.y, h01, l01);
            bf16_split2(v.z, v.w, h23, l23);
            *reinterpret_cast<__nv_bfloat162*>(&Bhi[row][c0])     = h01;
            *reinterpret_cast<__nv_bfloat162*>(&Bhi[row][c0 + 2]) = h23;
            *reinterpret_cast<__nv_bfloat162*>(&Blo[row][c0])     = l01;
            *reinterpret_cast<__nv_bfloat162*>(&Blo[row][c0 + 2]) = l23;
        }
        __syncthreads();

        #pragma unroll
        for (int ks = 0; ks < 2; ++ks) {
            wmma::load_matrix_sync(a_hi, &Ahi[wid * 16][ks * 16], 40);
            wmma::load_matrix_sync(a_lo, &Alo[wid * 16][ks * 16], 40);
            #pragma unroll
            for (int nt = 0; nt < 8; ++nt) {
                wmma::load_matrix_sync(b_hi, &Bhi[ks * 16][nt * 16], 136);
                wmma::load_matrix_sync(b_lo, &Blo[ks * 16][nt * 16], 136);
                wmma::mma_sync(acc[nt], a_hi, b_hi, acc[nt]);
                wmma::mma_sync(acc[nt], a_lo, b_hi, acc[nt]);
                wmma::mma_sync(acc[nt], a_hi, b_lo, acc[nt]);
            }
        }
        __syncthreads();
    }

    // --- bias step: out += frac[row] * bm[col], as one K=16 MMA ---
    for (int idx = t; idx < 128 * 16; idx += 256) {
        int r = idx >> 4, c = idx & 15;
        float v = (c == 0) ? s_frac[r] : 0.0f;
        bf16_split(v, Ahi[r][c], Alo[r][c]);
    }
    for (int idx = t; idx < 16 * 128; idx += 256) {
        int r = idx >> 7, c = idx & 127;
        float v = (r == 0) ? __ldg(&bm[c]) : 0.0f;
        bf16_split(v, Bhi[r][c], Blo[r][c]);
    }
    __syncthreads();

    wmma::load_matrix_sync(a_hi, &Ahi[wid * 16][0], 40);
    wmma::load_matrix_sync(a_lo, &Alo[wid * 16][0], 40);
    #pragma unroll
    for (int nt = 0; nt < 8; ++nt) {
        wmma::load_matrix_sync(b_hi, &Bhi[0][nt * 16], 136);
        wmma::load_matrix_sync(b_lo, &Blo[0][nt * 16], 136);
        wmma::mma_sync(acc[nt], a_hi, b_hi, acc[nt]);
        wmma::mma_sync(acc[nt], a_lo, b_hi, acc[nt]);
        wmma::mma_sync(acc[nt], a_hi, b_lo, acc[nt]);
    }

    // direct store (all rows valid thanks to the s0 clamp)
    #pragma unroll
    for (int nt = 0; nt < 8; ++nt) {
        wmma::store_matrix_sync(out + (size_t)(s0 + wid * 16) * DIM + nt * 16,
                                acc[nt], DIM, wmma::mem_row_major);
    }
}

// ---------------------------------------------------------------------------
// Launch: inputs (metadata order): x, index, weights, Wg, bg, Wm, bm
// ---------------------------------------------------------------------------
extern "C" void kernel_launch(void* const* d_in, const int* in_sizes, int n_in,
                              void* d_out, int out_size)
{
    const float* x       = (const float*)d_in[0];
    const int*   index   = (const int*)  d_in[1];
    const float* weights = (const float*)d_in[2];
    const float* Wg      = (const float*)d_in[3];
    const float* bg      = (const float*)d_in[4];
    const float* Wm      = (const float*)d_in[5];
    const float* bm      = (const float*)d_in[6];
    float*       out     = (float*)d_out;

    zero_scratch_kernel<<<4096, 256>>>();

    const int n_warps  = (N_TOTAL + NODES_PER_WARP - 1) / NODES_PER_WARP; // 7813
    const int n_blocks = (n_warps + 7) / 8;                               // 977
    pass1_kernel<<<n_blocks, 256>>>(x, index, weights, Wg, bg);

    const int gemm_blocks = (S_SEG + 127) / 128;                          // 977
    gemm_tc_kernel<<<gemm_blocks, 256>>>(Wm, bm, out);
}